// round 9
// baseline (speedup 1.0000x reference)
#include <cuda_runtime.h>
#include <cuda_bf16.h>
#include <cuda_fp16.h>
#include <math.h>
#include <cstdint>

#define Bdim 2
#define Ldim 2048
#define Edim 1024
#define Hdim 16
#define Ddim 64
#define NROWS (Bdim * Ldim)  // 4096
#define NBH (Bdim * Hdim)    // 32

// log2(e)^2 folding: c2*d2 inside sqrt gives log2(e)*d directly
#define C2 2.0813689810056077f
#define NEG2C2 (-4.1627379620112154f)

// Scratch (allocation-free rule: __device__ globals)
__device__ float g_rX[3][(size_t)NROWS * Edim];   // rna-rounded Q,K,V inputs
__device__ float g_rW[3][(size_t)Edim * Edim];    // rna-rounded Wq,Wk,Wv
__device__ float g_v[(size_t)NROWS * Edim];       // v projection (fp32)
__device__ float g_qkf[2][(size_t)NBH * Ldim * Ddim];       // q,k heads fp32 head-major (for norms)
__device__ unsigned short g_qh[(size_t)NBH * Ldim * Ddim];  // q heads bf16 [bh][l][d]
__device__ unsigned short g_kh[(size_t)NBH * Ldim * Ddim];  // k heads bf16 [bh][l][d]
__device__ float g_q2[NBH * Ldim];                // C2 * ||q||^2 (fp32-derived!)
__device__ float g_k2[NBH * Ldim];                // C2 * ||k||^2 (fp32-derived!)
__device__ float g_invZ[NBH * Ldim];
__device__ float g_w[NBH * Ldim];
__device__ float g_ho[Bdim * Edim];
__device__ unsigned short g_e[(size_t)NBH * Ldim * Ldim];  // exp scores, f16 (scaled 4096x)

// ======================================================================
// Helpers (plain sm_103 target: mma.sync + cp.async only)
// ======================================================================
__device__ __forceinline__ uint32_t smem_to_u32(const void* smem_ptr) {
    uint32_t addr;
    asm("{ .reg .u64 tmp; cvta.to.shared.u64 tmp, %1; cvt.u32.u64 %0, tmp; }"
        : "=r"(addr) : "l"(smem_ptr));
    return addr;
}
__device__ __forceinline__ void cp_async16(uint32_t s, const void* g) {
    asm volatile("cp.async.cg.shared.global [%0], [%1], 16;" :: "r"(s), "l"(g) : "memory");
}
__device__ __forceinline__ void cp_commit() {
    asm volatile("cp.async.commit_group;" ::: "memory");
}
template <int N>
__device__ __forceinline__ void cp_wait() {
    asm volatile("cp.async.wait_group %0;" :: "n"(N) : "memory");
}
__device__ __forceinline__ uint32_t f2tf(float x) {
    uint32_t r;
    asm("cvt.rna.tf32.f32 %0, %1;" : "=r"(r) : "f"(x));
    return r;
}
__device__ __forceinline__ float fast_sqrt(float x) {
    float r; asm("sqrt.approx.f32 %0, %1;" : "=f"(r) : "f"(x)); return r;
}
// packed f16x2 exp2 — one MUFU op, two results. Arg quantization error is
// incoherent per (q,k) -> averages out in w (verified by R7==R8 rel_err).
__device__ __forceinline__ uint32_t h2_ex2(uint32_t x) {
    uint32_t r;
    asm("ex2.approx.f16x2 %0, %1;" : "=r"(r) : "r"(x));
    return r;
}
__device__ __forceinline__ void mma_tf32(float c[4], const uint32_t a[4], const uint32_t b[2]) {
    asm volatile(
        "mma.sync.aligned.m16n8k8.row.col.f32.tf32.tf32.f32 "
        "{%0,%1,%2,%3}, {%4,%5,%6,%7}, {%8,%9}, {%0,%1,%2,%3};"
        : "+f"(c[0]), "+f"(c[1]), "+f"(c[2]), "+f"(c[3])
        : "r"(a[0]), "r"(a[1]), "r"(a[2]), "r"(a[3]), "r"(b[0]), "r"(b[1]));
}
__device__ __forceinline__ void mma_bf16(float c[4], const uint32_t a[4], const uint32_t b[2]) {
    asm volatile(
        "mma.sync.aligned.m16n8k16.row.col.f32.bf16.bf16.f32 "
        "{%0,%1,%2,%3}, {%4,%5,%6,%7}, {%8,%9}, {%0,%1,%2,%3};"
        : "+f"(c[0]), "+f"(c[1]), "+f"(c[2]), "+f"(c[3])
        : "r"(a[0]), "r"(a[1]), "r"(a[2]), "r"(a[3]), "r"(b[0]), "r"(b[1]));
}

// ======================================================================
// Pre-round all inputs to tf32 (rna) once: proj inner loop loses its cvts.
// ======================================================================
__global__ void __launch_bounds__(256) round_kernel(
    const float* __restrict__ Q, const float* __restrict__ K, const float* __restrict__ V,
    const float* __restrict__ Wq, const float* __restrict__ Wk, const float* __restrict__ Wv)
{
    const int a = blockIdx.y;
    const float* srcs[6] = {Q, K, V, Wq, Wk, Wv};
    float* dsts[6] = {g_rX[0], g_rX[1], g_rX[2], g_rW[0], g_rW[1], g_rW[2]};
    const int nvec = (a < 3) ? (NROWS * Edim / 4) : (Edim * Edim / 4);
    int i = blockIdx.x * 256 + threadIdx.x;
    if (i >= nvec) return;
    float4 v = ((const float4*)srcs[a])[i];
    v.x = __uint_as_float(f2tf(v.x));
    v.y = __uint_as_float(f2tf(v.y));
    v.z = __uint_as_float(f2tf(v.z));
    v.w = __uint_as_float(f2tf(v.w));
    ((float4*)dsts[a])[i] = v;
}

// ======================================================================
// Projection GEMM (mma.sync tf32, pre-rounded inputs):  C = X @ W^T
// z=0 (q), z=1 (k): epilogue writes bf16 head-major g_qh/g_kh AND fp32
//                   head-major g_qkf (for fp32-derived norms).
// z=2 (v): epilogue writes fp32 g_v.
// ======================================================================
#define PJST 36
#define PJ_TILE_FLOATS (128 * PJST)
#define PJ_BUF_FLOATS (2 * PJ_TILE_FLOATS)
#define PJ_SMEM_BYTES (2 * PJ_BUF_FLOATS * 4)

__global__ void __launch_bounds__(256) proj_mma_kernel()
{
    extern __shared__ float smem[];
    const uint32_t smem_u32 = smem_to_u32(smem);

    const int z = blockIdx.z;
    const float* __restrict__ X = g_rX[z];
    const float* __restrict__ W = g_rW[z];
    const int m0 = blockIdx.x * 128;
    const int n0 = blockIdx.y * 128;

    const int tid = threadIdx.x;
    const int wid = tid >> 5;
    const int lane = tid & 31;
    const int g = lane >> 2;
    const int t = lane & 3;
    const int wm = (wid >> 2) * 64;
    const int wn = (wid & 3) * 32;

    float c[4][4][4];
#pragma unroll
    for (int mi = 0; mi < 4; mi++)
#pragma unroll
        for (int ni = 0; ni < 4; ni++)
#pragma unroll
            for (int r = 0; r < 4; r++) c[mi][ni][r] = 0.f;

    auto load_chunk = [&](int cc) {
        const int k0 = cc * 32;
        uint32_t abase = smem_u32 + (uint32_t)((cc & 1) * PJ_BUF_FLOATS) * 4u;
#pragma unroll
        for (int it = 0; it < 4; it++) {
            int idx = tid + it * 256;
            int row = idx >> 3;
            int q = idx & 7;
            uint32_t soff = (uint32_t)(row * PJST + q * 4) * 4u;
            cp_async16(abase + soff, &X[(size_t)(m0 + row) * Edim + k0 + q * 4]);
            cp_async16(abase + (uint32_t)PJ_TILE_FLOATS * 4u + soff,
                       &W[(size_t)(n0 + row) * Edim + k0 + q * 4]);
        }
        cp_commit();
    };

    load_chunk(0);

    for (int cc = 0; cc < 32; cc++) {
        if (cc + 1 < 32) {
            load_chunk(cc + 1);
            cp_wait<1>();
        } else {
            cp_wait<0>();
        }
        __syncthreads();

        const float* As_ = smem + (cc & 1) * PJ_BUF_FLOATS;
        const float* Bs_ = As_ + PJ_TILE_FLOATS;

#pragma unroll
        for (int ks = 0; ks < 4; ks++) {
            const int k0 = ks * 8;
            uint32_t a[4][4], bf[4][2];
#pragma unroll
            for (int mi = 0; mi < 4; mi++) {
                const float* ap = As_ + (wm + mi * 16 + g) * PJST + k0 + t;
                a[mi][0] = __float_as_uint(ap[0]);
                a[mi][1] = __float_as_uint(ap[8 * PJST]);
                a[mi][2] = __float_as_uint(ap[4]);
                a[mi][3] = __float_as_uint(ap[8 * PJST + 4]);
            }
#pragma unroll
            for (int ni = 0; ni < 4; ni++) {
                const float* bp = Bs_ + (wn + ni * 8 + g) * PJST + k0 + t;
                bf[ni][0] = __float_as_uint(bp[0]);
                bf[ni][1] = __float_as_uint(bp[4]);
            }
#pragma unroll
            for (int mi = 0; mi < 4; mi++)
#pragma unroll
                for (int ni = 0; ni < 4; ni++) mma_tf32(c[mi][ni], a[mi], bf[ni]);
        }
        __syncthreads();
    }

    if (z == 2) {
#pragma unroll
        for (int mi = 0; mi < 4; mi++) {
            int row = m0 + wm + mi * 16 + g;
#pragma unroll
            for (int ni = 0; ni < 4; ni++) {
                int col = n0 + wn + ni * 8 + 2 * t;
                *(float2*)&g_v[(size_t)row * Edim + col] = make_float2(c[mi][ni][0], c[mi][ni][1]);
                *(float2*)&g_v[(size_t)(row + 8) * Edim + col] = make_float2(c[mi][ni][2], c[mi][ni][3]);
            }
        }
    } else {
        unsigned short* dst = z ? g_kh : g_qh;
        float* dstf = g_qkf[z];
#pragma unroll
        for (int mi = 0; mi < 4; mi++) {
            int row = m0 + wm + mi * 16 + g;
            int b = row >> 11;
            int l = row & 2047;
#pragma unroll
            for (int ni = 0; ni < 4; ni++) {
                int col = n0 + wn + ni * 8 + 2 * t;
                int h = col >> 6;
                int d = col & 63;
                size_t i0 = (((size_t)(b * Hdim + h) * Ldim + l) * Ddim + d);
                __nv_bfloat162 lo = __float22bfloat162_rn(make_float2(c[mi][ni][0], c[mi][ni][1]));
                __nv_bfloat162 hi = __float22bfloat162_rn(make_float2(c[mi][ni][2], c[mi][ni][3]));
                *(__nv_bfloat162*)&dst[i0] = lo;
                *(__nv_bfloat162*)&dst[i0 + (size_t)8 * Ddim] = hi;  // row+8, same b
                *(float2*)&dstf[i0] = make_float2(c[mi][ni][0], c[mi][ni][1]);
                *(float2*)&dstf[i0 + (size_t)8 * Ddim] = make_float2(c[mi][ni][2], c[mi][ni][3]);
            }
        }
    }
}

// ======================================================================
// Prep: C2 * row sumsq of FP32 head rows (coherent-bias-free norms).
// One warp per (arr, bh, l).
// ======================================================================
__global__ void __launch_bounds__(256) prep_kernel()
{
    const int gwid = blockIdx.x * 8 + (threadIdx.x >> 5);
    const int lane = threadIdx.x & 31;
    const int arr = gwid >> 16;          // 0 = q, 1 = k
    const int rem = gwid & 65535;
    const int bh = rem >> 11;
    const int l = rem & 2047;
    const float* src = g_qkf[arr] + ((size_t)bh * Ldim + l) * Ddim;
    float2 v = ((const float2*)src)[lane];
    float s = v.x * v.x + v.y * v.y;
#pragma unroll
    for (int off = 16; off; off >>= 1) s += __shfl_xor_sync(0xffffffffu, s, off);
    if (lane == 0) (arr ? g_k2 : g_q2)[bh * Ldim + l] = C2 * s;
}

// ======================================================================
// Attention pass A: bf16 m16n8k16 QK^T.
// arg = 12 - sqrt(max(C2*(q2+k2) - 2*C2*qk, 0));  e' = 2^arg via f16x2 MUFU
//     = 4096 * exp(-L2dist). Z' sums the stored f16 values (consistent).
// ======================================================================
#define A_Q_BYTES (128 * 144)
#define A_K_BYTES (128 * 144)
#define A_SMEM_BYTES (A_Q_BYTES + 2 * A_K_BYTES + 512)

__global__ void __launch_bounds__(256, 2) attn_passA_kernel()
{
    extern __shared__ char smc[];
    char* qsc = smc;
    char* ksc = smc + A_Q_BYTES;
    float* zsh = (float*)(smc + A_Q_BYTES + 2 * A_K_BYTES);
    const uint32_t qs_u = smem_to_u32(qsc);
    const uint32_t ks_u = smem_to_u32(ksc);

    const int tid = threadIdx.x;
    const int wid = tid >> 5;
    const int lane = tid & 31;
    const int g = lane >> 2;
    const int t = lane & 3;
    const int wm = (wid >> 2) * 64;
    const int wn = (wid & 3) * 32;
    const int bh = blockIdx.y;
    const int qbase = blockIdx.x * 128;

    if (tid < 128) zsh[tid] = 0.f;

    const unsigned short* gq = g_qh + ((size_t)bh * Ldim + qbase) * Ddim;
    const unsigned short* gk = g_kh + (size_t)bh * Ldim * Ddim;

#pragma unroll
    for (int it = 0; it < 4; it++) {
        int idx = tid + it * 256;
        int r = idx >> 3;
        int ch = idx & 7;
        cp_async16(qs_u + (uint32_t)(r * 144 + ch * 16), gq + (size_t)r * Ddim + ch * 8);
    }
    cp_commit();

    auto load_k = [&](int jt) {
        uint32_t base = ks_u + (uint32_t)((jt & 1) * A_K_BYTES);
#pragma unroll
        for (int it = 0; it < 4; it++) {
            int idx = tid + it * 256;
            int r = idx >> 3;
            int ch = idx & 7;
            cp_async16(base + (uint32_t)(r * 144 + ch * 16),
                       gk + (size_t)(jt * 128 + r) * Ddim + ch * 8);
        }
        cp_commit();
    };

    load_k(0);
    cp_wait<1>();
    __syncthreads();

    float q2r[8];
    const float* q2p = g_q2 + bh * Ldim + qbase;
#pragma unroll
    for (int i = 0; i < 8; i++) q2r[i] = q2p[wm + (i >> 1) * 16 + (i & 1) * 8 + g];

    unsigned short* pe0 = g_e + ((size_t)bh * Ldim + qbase + wm + g) * Ldim + wn + 2 * t;

    float zloc[8];
#pragma unroll
    for (int i = 0; i < 8; i++) zloc[i] = 0.f;

    for (int jt = 0; jt < 16; jt++) {
        if (jt + 1 < 16) {
            load_k(jt + 1);
            cp_wait<1>();
        } else {
            cp_wait<0>();
        }
        __syncthreads();

        const char* kb = ksc + (jt & 1) * A_K_BYTES;

        float c[4][4][4];
#pragma unroll
        for (int mi = 0; mi < 4; mi++)
#pragma unroll
            for (int ni = 0; ni < 4; ni++)
#pragma unroll
                for (int r = 0; r < 4; r++) c[mi][ni][r] = 0.f;

#pragma unroll
        for (int ks = 0; ks < 4; ks++) {
            uint32_t a[4][4], bf[4][2];
#pragma unroll
            for (int mi = 0; mi < 4; mi++) {
                const char* ap = qsc + (wm + mi * 16 + g) * 144 + ks * 32 + t * 4;
                a[mi][0] = *(const uint32_t*)(ap);
                a[mi][1] = *(const uint32_t*)(ap + 8 * 144);
                a[mi][2] = *(const uint32_t*)(ap + 16);
                a[mi][3] = *(const uint32_t*)(ap + 8 * 144 + 16);
            }
#pragma unroll
            for (int ni = 0; ni < 4; ni++) {
                const char* bp = kb + (wn + ni * 8 + g) * 144 + ks * 32 + t * 4;
                bf[ni][0] = *(const uint32_t*)(bp);
                bf[ni][1] = *(const uint32_t*)(bp + 16);
            }
#pragma unroll
            for (int mi = 0; mi < 4; mi++)
#pragma unroll
                for (int ni = 0; ni < 4; ni++) mma_bf16(c[mi][ni], a[mi], bf[ni]);
        }

        const float* k2p = g_k2 + bh * Ldim + jt * 128;
        unsigned short* pet = pe0 + jt * 128;
#pragma unroll
        for (int ni = 0; ni < 4; ni++) {
            float2 k2c = *(const float2*)&k2p[wn + ni * 8 + 2 * t];
#pragma unroll
            for (int mi = 0; mi < 4; mi++) {
#pragma unroll
                for (int half = 0; half < 2; half++) {
                    float s0 = fmaf(NEG2C2, c[mi][ni][half * 2 + 0], q2r[mi * 2 + half] + k2c.x);
                    float s1 = fmaf(NEG2C2, c[mi][ni][half * 2 + 1], q2r[mi * 2 + half] + k2c.y);
                    float a0 = 12.f - fast_sqrt(fmaxf(s0, 0.f));
                    float a1 = 12.f - fast_sqrt(fmaxf(s1, 0.f));
                    __half2 hh = __floats2half2_rn(a0, a1);
                    uint32_t ee = h2_ex2(*(const uint32_t*)&hh);
                    float2 ef = __half22float2(*(const __half2*)&ee);
                    zloc[mi * 2 + half] += ef.x + ef.y;
                    *(uint32_t*)(pet + (size_t)(mi * 16 + half * 8) * Ldim + ni * 8) = ee;
                }
            }
        }
        __syncthreads();
    }

#pragma unroll
    for (int i = 0; i < 8; i++) {
        float z = zloc[i];
        z += __shfl_xor_sync(0xffffffffu, z, 1);
        z += __shfl_xor_sync(0xffffffffu, z, 2);
        if (t == 0) atomicAdd(&zsh[wm + (i >> 1) * 16 + (i & 1) * 8 + g], z);
    }
    __syncthreads();
    if (tid < 128) g_invZ[bh * Ldim + qbase + tid] = 1.f / zsh[tid];
}

// ======================================================================
// Zero accumulators g_ho (2048) and g_w (65536)
// ======================================================================
__global__ void zero_acc_kernel()
{
    int i = blockIdx.x * blockDim.x + threadIdx.x;
    if (i < Bdim * Edim) g_ho[i] = 0.f;
    if (i < NBH * Ldim) g_w[i] = 0.f;
}

// ======================================================================
// Pass B: w_k = sum_q e'[bh][q][k] * invZ'[bh][q]  (f16 e, scale cancels)
// ======================================================================
__global__ void __launch_bounds__(256) attn_passB_kernel()
{
    __shared__ float invz[512];
    __shared__ float wsm[8][128];

    const int tid = threadIdx.x;
    const int wid = tid >> 5;
    const int lane = tid & 31;
    const int bh = blockIdx.y;
    const int kbase = blockIdx.x * 128;
    const int qslice = blockIdx.z * 512;

    for (int i = tid; i < 512; i += 256) invz[i] = g_invZ[bh * Ldim + qslice + i];
    __syncthreads();

    const unsigned short* pe =
        g_e + ((size_t)bh * Ldim + qslice + wid) * Ldim + kbase + lane * 4;

    float acc[4];
#pragma unroll
    for (int j = 0; j < 4; j++) acc[j] = 0.f;

#pragma unroll 8
    for (int q = wid; q < 512; q += 8) {
        uint2 raw = *(const uint2*)pe;
        float iz = invz[q];
        float2 e0 = __half22float2(*(const __half2*)&raw.x);
        float2 e1 = __half22float2(*(const __half2*)&raw.y);
        acc[0] = fmaf(e0.x, iz, acc[0]);
        acc[1] = fmaf(e0.y, iz, acc[1]);
        acc[2] = fmaf(e1.x, iz, acc[2]);
        acc[3] = fmaf(e1.y, iz, acc[3]);
        pe += (size_t)8 * Ldim;
    }
#pragma unroll
    for (int j = 0; j < 4; j++) wsm[wid][lane * 4 + j] = acc[j];
    __syncthreads();
    if (tid < 128) {
        float s = 0.f;
#pragma unroll
        for (int wq = 0; wq < 8; wq++) s += wsm[wq][tid];
        atomicAdd(&g_w[bh * Ldim + kbase + tid], s);
    }
}

// ======================================================================
// GEMV: g_ho[b, h*64+d] = sum_k w[bh][k] * v[b,k][h*64+d]
// ======================================================================
__global__ void __launch_bounds__(256) gemv_ho_kernel()
{
    __shared__ float red[4][64];
    const int tid = threadIdx.x;
    const int bh = blockIdx.x;
    const int b = bh >> 4;
    const int h = bh & 15;
    const int kbase = blockIdx.y * 256;
    const int d = tid & 63;
    const int kq = tid >> 6;

    const float* vv = g_v + (size_t)(b * Ldim) * Edim + h * Ddim + d;
    const float* wp = g_w + bh * Ldim;

    float acc = 0.f;
#pragma unroll 8
    for (int k = kbase + kq; k < kbase + 256; k += 4)
        acc = fmaf(wp[k], vv[(size_t)k * Edim], acc);

    red[kq][d] = acc;
    __syncthreads();
    if (tid < 64) {
        float s = red[0][tid] + red[1][tid] + red[2][tid] + red[3][tid];
        atomicAdd(&g_ho[b * Edim + h * Ddim + tid], s);
    }
}

// ======================================================================
// Final: out[b, e'] = sum_e ho[b, e] * Wo[e', e]   (warp per output)
// ======================================================================
__global__ void __launch_bounds__(256) out_kernel(const float* __restrict__ Wo,
                                                  float* __restrict__ out)
{
    int gw = (blockIdx.x * blockDim.x + threadIdx.x) >> 5;
    int lane = threadIdx.x & 31;
    int b = gw >> 10;
    int ep = gw & 1023;
    const float* ho = &g_ho[(size_t)b * Edim];
    const float* wr = &Wo[(size_t)ep * Edim];
    float s = 0.f;
    for (int e = lane * 4; e < Edim; e += 128) {
        float4 w4 = *(const float4*)&wr[e];
        float4 h4 = *(const float4*)&ho[e];
        s = fmaf(w4.x, h4.x, s);
        s = fmaf(w4.y, h4.y, s);
        s = fmaf(w4.z, h4.z, s);
        s = fmaf(w4.w, h4.w, s);
    }
#pragma unroll
    for (int off = 16; off; off >>= 1) s += __shfl_xor_sync(0xffffffffu, s, off);
    if (lane == 0) out[(size_t)b * Edim + ep] = s;
}

// ======================================================================
extern "C" void kernel_launch(void* const* d_in, const int* in_sizes, int n_in,
                              void* d_out, int out_size)
{
    const float* Q = (const float*)d_in[0];
    const float* K = (const float*)d_in[1];
    const float* V = (const float*)d_in[2];
    const float* Wq = (const float*)d_in[3];
    const float* Wk = (const float*)d_in[4];
    const float* Wv = (const float*)d_in[5];
    const float* Wo = (const float*)d_in[6];
    float* out = (float*)d_out;

    cudaFuncSetAttribute(proj_mma_kernel, cudaFuncAttributeMaxDynamicSharedMemorySize, PJ_SMEM_BYTES);
    cudaFuncSetAttribute(attn_passA_kernel, cudaFuncAttributeMaxDynamicSharedMemorySize, A_SMEM_BYTES);

    round_kernel<<<dim3(4096, 6), 256>>>(Q, K, V, Wq, Wk, Wv);
    proj_mma_kernel<<<dim3(NROWS / 128, Edim / 128, 3), 256, PJ_SMEM_BYTES>>>();
    prep_kernel<<<16384, 256>>>();
    attn_passA_kernel<<<dim3(Ldim / 128, NBH), 256, A_SMEM_BYTES>>>();
    zero_acc_kernel<<<64, 1024>>>();
    attn_passB_kernel<<<dim3(Ldim / 128, NBH, 4), 256>>>();
    gemv_ho_kernel<<<dim3(NBH, Ldim / 256), 256>>>();
    out_kernel<<<256, 256>>>(Wo, out);
}

// round 10
// speedup vs baseline: 1.1773x; 1.1773x over previous
#include <cuda_runtime.h>
#include <cuda_bf16.h>
#include <cuda_fp16.h>
#include <math.h>
#include <cstdint>

#define Bdim 2
#define Ldim 2048
#define Edim 1024
#define Hdim 16
#define Ddim 64
#define NROWS (Bdim * Ldim)  // 4096
#define NBH (Bdim * Hdim)    // 32

// log2(e)^2 folding: C2*d2 inside sqrt gives log2(e)*d directly
#define C2 2.0813689810056077f
#define NEG2C2 (-4.1627379620112154f)

// Scratch (allocation-free rule: __device__ globals)
__device__ float g_v[(size_t)NROWS * Edim];                 // v projection (fp32)
__device__ unsigned short g_qh[(size_t)NROWS * Edim];       // q proj, bf16, row-major (B,L,E)
__device__ unsigned short g_kh[(size_t)NROWS * Edim];       // k proj, bf16, row-major (B,L,E)
__device__ float g_q2[NBH * Ldim];                // C2 * ||q||^2 (fp32-derived, accumulated)
__device__ float g_k2[NBH * Ldim];                // C2 * ||k||^2
__device__ float g_invZ[NBH * Ldim];
__device__ float g_w[NBH * Ldim];
__device__ float g_ho[Bdim * Edim];
__device__ unsigned short g_e[(size_t)NBH * Ldim * Ldim];  // exp scores, f16 (scaled 4096x)

// ======================================================================
// Helpers (plain sm_103 target: mma.sync + cp.async only)
// ======================================================================
__device__ __forceinline__ uint32_t smem_to_u32(const void* smem_ptr) {
    uint32_t addr;
    asm("{ .reg .u64 tmp; cvta.to.shared.u64 tmp, %1; cvt.u32.u64 %0, tmp; }"
        : "=r"(addr) : "l"(smem_ptr));
    return addr;
}
__device__ __forceinline__ void cp_async16(uint32_t s, const void* g) {
    asm volatile("cp.async.cg.shared.global [%0], [%1], 16;" :: "r"(s), "l"(g) : "memory");
}
__device__ __forceinline__ void cp_commit() {
    asm volatile("cp.async.commit_group;" ::: "memory");
}
template <int N>
__device__ __forceinline__ void cp_wait() {
    asm volatile("cp.async.wait_group %0;" :: "n"(N) : "memory");
}
__device__ __forceinline__ uint32_t f2tf(float x) {
    uint32_t r;
    asm("cvt.rna.tf32.f32 %0, %1;" : "=r"(r) : "f"(x));
    return r;
}
__device__ __forceinline__ float fast_sqrt(float x) {
    float r; asm("sqrt.approx.f32 %0, %1;" : "=f"(r) : "f"(x)); return r;
}
// packed f16x2 exp2 — one MUFU op, two results. Arg quantization error is
// incoherent per (q,k) -> averages out in w (verified R7==R8, R9 passes).
__device__ __forceinline__ uint32_t h2_ex2(uint32_t x) {
    uint32_t r;
    asm("ex2.approx.f16x2 %0, %1;" : "=r"(r) : "r"(x));
    return r;
}
__device__ __forceinline__ void mma_tf32(float c[4], const uint32_t a[4], const uint32_t b[2]) {
    asm volatile(
        "mma.sync.aligned.m16n8k8.row.col.f32.tf32.tf32.f32 "
        "{%0,%1,%2,%3}, {%4,%5,%6,%7}, {%8,%9}, {%0,%1,%2,%3};"
        : "+f"(c[0]), "+f"(c[1]), "+f"(c[2]), "+f"(c[3])
        : "r"(a[0]), "r"(a[1]), "r"(a[2]), "r"(a[3]), "r"(b[0]), "r"(b[1]));
}
__device__ __forceinline__ void mma_bf16(float c[4], const uint32_t a[4], const uint32_t b[2]) {
    asm volatile(
        "mma.sync.aligned.m16n8k16.row.col.f32.bf16.bf16.f32 "
        "{%0,%1,%2,%3}, {%4,%5,%6,%7}, {%8,%9}, {%0,%1,%2,%3};"
        : "+f"(c[0]), "+f"(c[1]), "+f"(c[2]), "+f"(c[3])
        : "r"(a[0]), "r"(a[1]), "r"(a[2]), "r"(a[3]), "r"(b[0]), "r"(b[1]));
}

// ======================================================================
// Zero accumulators: g_ho, g_w, g_q2, g_k2 (runs BEFORE proj — norms are
// accumulated by proj's epilogue via atomics)
// ======================================================================
__global__ void zero_acc_kernel()
{
    int i = blockIdx.x * blockDim.x + threadIdx.x;  // 0..65535
    if (i < Bdim * Edim) g_ho[i] = 0.f;
    g_w[i] = 0.f;
    g_q2[i] = 0.f;
    g_k2[i] = 0.f;
}

// ======================================================================
// Projection GEMM (mma.sync tf32, inline rna cvt):  C = X @ W^T
// z=0 (q), z=1 (k): epilogue writes bf16 row-major (coalesced) AND
//                   accumulates C2*||.||^2 per (row, head) via atomics.
// z=2 (v): epilogue writes fp32 g_v.
// ======================================================================
#define PJST 36
#define PJ_TILE_FLOATS (128 * PJST)
#define PJ_BUF_FLOATS (2 * PJ_TILE_FLOATS)
#define PJ_SMEM_BYTES (2 * PJ_BUF_FLOATS * 4 + 1024)  // + norm scratch

__global__ void __launch_bounds__(256) proj_mma_kernel(
    const float* __restrict__ Q, const float* __restrict__ K, const float* __restrict__ V,
    const float* __restrict__ Wq, const float* __restrict__ Wk, const float* __restrict__ Wv)
{
    extern __shared__ float smem[];
    const uint32_t smem_u32 = smem_to_u32(smem);

    const int z = blockIdx.z;
    const float* __restrict__ X = (z == 0) ? Q : ((z == 1) ? K : V);
    const float* __restrict__ W = (z == 0) ? Wq : ((z == 1) ? Wk : Wv);
    const int m0 = blockIdx.x * 128;
    const int n0 = blockIdx.y * 128;

    const int tid = threadIdx.x;
    const int wid = tid >> 5;
    const int lane = tid & 31;
    const int g = lane >> 2;
    const int t = lane & 3;
    const int wm = (wid >> 2) * 64;
    const int wn = (wid & 3) * 32;

    float c[4][4][4];
#pragma unroll
    for (int mi = 0; mi < 4; mi++)
#pragma unroll
        for (int ni = 0; ni < 4; ni++)
#pragma unroll
            for (int r = 0; r < 4; r++) c[mi][ni][r] = 0.f;

    auto load_chunk = [&](int cc) {
        const int k0 = cc * 32;
        uint32_t abase = smem_u32 + (uint32_t)((cc & 1) * PJ_BUF_FLOATS) * 4u;
#pragma unroll
        for (int it = 0; it < 4; it++) {
            int idx = tid + it * 256;
            int row = idx >> 3;
            int q = idx & 7;
            uint32_t soff = (uint32_t)(row * PJST + q * 4) * 4u;
            cp_async16(abase + soff, &X[(size_t)(m0 + row) * Edim + k0 + q * 4]);
            cp_async16(abase + (uint32_t)PJ_TILE_FLOATS * 4u + soff,
                       &W[(size_t)(n0 + row) * Edim + k0 + q * 4]);
        }
        cp_commit();
    };

    load_chunk(0);

    for (int cc = 0; cc < 32; cc++) {
        if (cc + 1 < 32) {
            load_chunk(cc + 1);
            cp_wait<1>();
        } else {
            cp_wait<0>();
        }
        __syncthreads();

        const float* As_ = smem + (cc & 1) * PJ_BUF_FLOATS;
        const float* Bs_ = As_ + PJ_TILE_FLOATS;

#pragma unroll
        for (int ks = 0; ks < 4; ks++) {
            const int k0 = ks * 8;
            uint32_t a[4][4], bf[4][2];
#pragma unroll
            for (int mi = 0; mi < 4; mi++) {
                const float* ap = As_ + (wm + mi * 16 + g) * PJST + k0 + t;
                a[mi][0] = f2tf(ap[0]);
                a[mi][1] = f2tf(ap[8 * PJST]);
                a[mi][2] = f2tf(ap[4]);
                a[mi][3] = f2tf(ap[8 * PJST + 4]);
            }
#pragma unroll
            for (int ni = 0; ni < 4; ni++) {
                const float* bp = Bs_ + (wn + ni * 8 + g) * PJST + k0 + t;
                bf[ni][0] = f2tf(bp[0]);
                bf[ni][1] = f2tf(bp[4]);
            }
#pragma unroll
            for (int mi = 0; mi < 4; mi++)
#pragma unroll
                for (int ni = 0; ni < 4; ni++) mma_tf32(c[mi][ni], a[mi], bf[ni]);
        }
        __syncthreads();
    }

    if (z == 2) {
#pragma unroll
        for (int mi = 0; mi < 4; mi++) {
            int row = m0 + wm + mi * 16 + g;
#pragma unroll
            for (int ni = 0; ni < 4; ni++) {
                int col = n0 + wn + ni * 8 + 2 * t;
                *(float2*)&g_v[(size_t)row * Edim + col] = make_float2(c[mi][ni][0], c[mi][ni][1]);
                *(float2*)&g_v[(size_t)(row + 8) * Edim + col] = make_float2(c[mi][ni][2], c[mi][ni][3]);
            }
        }
    } else {
        unsigned short* dst = z ? g_kh : g_qh;
        float* nrm = z ? g_k2 : g_q2;
        float* snorm = smem;  // 256 floats: [row128][head_local]; tiles no longer needed

        if (tid < 256) snorm[tid] = 0.f;

        // per-thread partial row sums (over this thread's 8 cols per row)
        float rsum[4][2];
#pragma unroll
        for (int mi = 0; mi < 4; mi++) {
#pragma unroll
            for (int half = 0; half < 2; half++) {
                float s = 0.f;
#pragma unroll
                for (int ni = 0; ni < 4; ni++) {
                    float v0 = c[mi][ni][half * 2 + 0];
                    float v1 = c[mi][ni][half * 2 + 1];
                    s = fmaf(v0, v0, s);
                    s = fmaf(v1, v1, s);
                }
                rsum[mi][half] = s;
            }
        }
        // quad reduce (t = lane&3): full 32-col warp-range row sums
#pragma unroll
        for (int mi = 0; mi < 4; mi++)
#pragma unroll
            for (int half = 0; half < 2; half++) {
                float s = rsum[mi][half];
                s += __shfl_xor_sync(0xffffffffu, s, 1);
                s += __shfl_xor_sync(0xffffffffu, s, 2);
                rsum[mi][half] = s;
            }
        __syncthreads();  // snorm zero visible
        const int hh = wn >> 6;  // 0 or 1: local head within CTA's 128 cols
        if (t == 0) {
#pragma unroll
            for (int mi = 0; mi < 4; mi++)
#pragma unroll
                for (int half = 0; half < 2; half++) {
                    int r128 = wm + mi * 16 + half * 8 + g;
                    atomicAdd(&snorm[r128 * 2 + hh], rsum[mi][half]);
                }
        }

        // bf16 row-major stores (coalesced)
#pragma unroll
        for (int mi = 0; mi < 4; mi++) {
            int row = m0 + wm + mi * 16 + g;
#pragma unroll
            for (int ni = 0; ni < 4; ni++) {
                int col = n0 + wn + ni * 8 + 2 * t;
                __nv_bfloat162 lo = __float22bfloat162_rn(make_float2(c[mi][ni][0], c[mi][ni][1]));
                __nv_bfloat162 hi = __float22bfloat162_rn(make_float2(c[mi][ni][2], c[mi][ni][3]));
                *(__nv_bfloat162*)&dst[(size_t)row * Edim + col] = lo;
                *(__nv_bfloat162*)&dst[(size_t)(row + 8) * Edim + col] = hi;
            }
        }

        __syncthreads();
        if (tid < 256) {
            int r128 = tid >> 1;
            int row = m0 + r128;
            int b = row >> 11;
            int l = row & 2047;
            int h = (n0 >> 6) + (tid & 1);
            atomicAdd(&nrm[(b * Hdim + h) * Ldim + l], C2 * snorm[tid]);
        }
    }
}

// ======================================================================
// Attention pass A: bf16 m16n8k16 QK^T from row-major bf16 proj.
// arg = 12 - sqrt(max(C2*(q2+k2) - 2*C2*qk, 0));  e' = 2^arg via f16x2 MUFU
//     = 4096 * exp(-L2dist). Z' sums the stored f16 values (consistent).
// ======================================================================
#define A_Q_BYTES (128 * 144)
#define A_K_BYTES (128 * 144)
#define A_SMEM_BYTES (A_Q_BYTES + 2 * A_K_BYTES + 512)

__global__ void __launch_bounds__(256, 2) attn_passA_kernel()
{
    extern __shared__ char smc[];
    char* qsc = smc;
    char* ksc = smc + A_Q_BYTES;
    float* zsh = (float*)(smc + A_Q_BYTES + 2 * A_K_BYTES);
    const uint32_t qs_u = smem_to_u32(qsc);
    const uint32_t ks_u = smem_to_u32(ksc);

    const int tid = threadIdx.x;
    const int wid = tid >> 5;
    const int lane = tid & 31;
    const int g = lane >> 2;
    const int t = lane & 3;
    const int wm = (wid >> 2) * 64;
    const int wn = (wid & 3) * 32;
    const int bh = blockIdx.y;
    const int b = bh >> 4;
    const int h = bh & 15;
    const int qbase = blockIdx.x * 128;

    if (tid < 128) zsh[tid] = 0.f;

    const unsigned short* gq = g_qh + (size_t)(b * Ldim + qbase) * Edim + h * Ddim;
    const unsigned short* gk = g_kh + (size_t)(b * Ldim) * Edim + h * Ddim;

#pragma unroll
    for (int it = 0; it < 4; it++) {
        int idx = tid + it * 256;
        int r = idx >> 3;
        int ch = idx & 7;
        cp_async16(qs_u + (uint32_t)(r * 144 + ch * 16), gq + (size_t)r * Edim + ch * 8);
    }
    cp_commit();

    auto load_k = [&](int jt) {
        uint32_t base = ks_u + (uint32_t)((jt & 1) * A_K_BYTES);
#pragma unroll
        for (int it = 0; it < 4; it++) {
            int idx = tid + it * 256;
            int r = idx >> 3;
            int ch = idx & 7;
            cp_async16(base + (uint32_t)(r * 144 + ch * 16),
                       gk + (size_t)(jt * 128 + r) * Edim + ch * 8);
        }
        cp_commit();
    };

    load_k(0);
    cp_wait<1>();
    __syncthreads();

    float q2r[8];
    const float* q2p = g_q2 + bh * Ldim + qbase;
#pragma unroll
    for (int i = 0; i < 8; i++) q2r[i] = q2p[wm + (i >> 1) * 16 + (i & 1) * 8 + g];

    unsigned short* pe0 = g_e + ((size_t)bh * Ldim + qbase + wm + g) * Ldim + wn + 2 * t;

    float zloc[8];
#pragma unroll
    for (int i = 0; i < 8; i++) zloc[i] = 0.f;

    for (int jt = 0; jt < 16; jt++) {
        if (jt + 1 < 16) {
            load_k(jt + 1);
            cp_wait<1>();
        } else {
            cp_wait<0>();
        }
        __syncthreads();

        const char* kb = ksc + (jt & 1) * A_K_BYTES;

        float c[4][4][4];
#pragma unroll
        for (int mi = 0; mi < 4; mi++)
#pragma unroll
            for (int ni = 0; ni < 4; ni++)
#pragma unroll
                for (int r = 0; r < 4; r++) c[mi][ni][r] = 0.f;

#pragma unroll
        for (int ks = 0; ks < 4; ks++) {
            uint32_t a[4][4], bf[4][2];
#pragma unroll
            for (int mi = 0; mi < 4; mi++) {
                const char* ap = qsc + (wm + mi * 16 + g) * 144 + ks * 32 + t * 4;
                a[mi][0] = *(const uint32_t*)(ap);
                a[mi][1] = *(const uint32_t*)(ap + 8 * 144);
                a[mi][2] = *(const uint32_t*)(ap + 16);
                a[mi][3] = *(const uint32_t*)(ap + 8 * 144 + 16);
            }
#pragma unroll
            for (int ni = 0; ni < 4; ni++) {
                const char* bp = kb + (wn + ni * 8 + g) * 144 + ks * 32 + t * 4;
                bf[ni][0] = *(const uint32_t*)(bp);
                bf[ni][1] = *(const uint32_t*)(bp + 16);
            }
#pragma unroll
            for (int mi = 0; mi < 4; mi++)
#pragma unroll
                for (int ni = 0; ni < 4; ni++) mma_bf16(c[mi][ni], a[mi], bf[ni]);
        }

        const float* k2p = g_k2 + bh * Ldim + jt * 128;
        unsigned short* pet = pe0 + jt * 128;
#pragma unroll
        for (int ni = 0; ni < 4; ni++) {
            float2 k2c = *(const float2*)&k2p[wn + ni * 8 + 2 * t];
#pragma unroll
            for (int mi = 0; mi < 4; mi++) {
#pragma unroll
                for (int half = 0; half < 2; half++) {
                    float s0 = fmaf(NEG2C2, c[mi][ni][half * 2 + 0], q2r[mi * 2 + half] + k2c.x);
                    float s1 = fmaf(NEG2C2, c[mi][ni][half * 2 + 1], q2r[mi * 2 + half] + k2c.y);
                    float a0 = 12.f - fast_sqrt(fmaxf(s0, 0.f));
                    float a1 = 12.f - fast_sqrt(fmaxf(s1, 0.f));
                    __half2 hh2 = __floats2half2_rn(a0, a1);
                    uint32_t ee = h2_ex2(*(const uint32_t*)&hh2);
                    float2 ef = __half22float2(*(const __half2*)&ee);
                    zloc[mi * 2 + half] += ef.x + ef.y;
                    *(uint32_t*)(pet + (size_t)(mi * 16 + half * 8) * Ldim + ni * 8) = ee;
                }
            }
        }
        __syncthreads();
    }

#pragma unroll
    for (int i = 0; i < 8; i++) {
        float z = zloc[i];
        z += __shfl_xor_sync(0xffffffffu, z, 1);
        z += __shfl_xor_sync(0xffffffffu, z, 2);
        if (t == 0) atomicAdd(&zsh[wm + (i >> 1) * 16 + (i & 1) * 8 + g], z);
    }
    __syncthreads();
    if (tid < 128) g_invZ[bh * Ldim + qbase + tid] = 1.f / zsh[tid];
}

// ======================================================================
// Pass B: w_k = sum_q e'[bh][q][k] * invZ'[bh][q]  (f16 e, scale cancels)
// ======================================================================
__global__ void __launch_bounds__(256) attn_passB_kernel()
{
    __shared__ float invz[512];
    __shared__ float wsm[8][128];

    const int tid = threadIdx.x;
    const int wid = tid >> 5;
    const int lane = tid & 31;
    const int bh = blockIdx.y;
    const int kbase = blockIdx.x * 128;
    const int qslice = blockIdx.z * 512;

    for (int i = tid; i < 512; i += 256) invz[i] = g_invZ[bh * Ldim + qslice + i];
    __syncthreads();

    const unsigned short* pe =
        g_e + ((size_t)bh * Ldim + qslice + wid) * Ldim + kbase + lane * 4;

    float acc[4];
#pragma unroll
    for (int j = 0; j < 4; j++) acc[j] = 0.f;

#pragma unroll 8
    for (int q = wid; q < 512; q += 8) {
        uint2 raw = *(const uint2*)pe;
        float iz = invz[q];
        float2 e0 = __half22float2(*(const __half2*)&raw.x);
        float2 e1 = __half22float2(*(const __half2*)&raw.y);
        acc[0] = fmaf(e0.x, iz, acc[0]);
        acc[1] = fmaf(e0.y, iz, acc[1]);
        acc[2] = fmaf(e1.x, iz, acc[2]);
        acc[3] = fmaf(e1.y, iz, acc[3]);
        pe += (size_t)8 * Ldim;
    }
#pragma unroll
    for (int j = 0; j < 4; j++) wsm[wid][lane * 4 + j] = acc[j];
    __syncthreads();
    if (tid < 128) {
        float s = 0.f;
#pragma unroll
        for (int wq = 0; wq < 8; wq++) s += wsm[wq][tid];
        atomicAdd(&g_w[bh * Ldim + kbase + tid], s);
    }
}

// ======================================================================
// GEMV: g_ho[b, h*64+d] = sum_k w[bh][k] * v[b,k][h*64+d]
// ======================================================================
__global__ void __launch_bounds__(256) gemv_ho_kernel()
{
    __shared__ float red[4][64];
    const int tid = threadIdx.x;
    const int bh = blockIdx.x;
    const int b = bh >> 4;
    const int h = bh & 15;
    const int kbase = blockIdx.y * 256;
    const int d = tid & 63;
    const int kq = tid >> 6;

    const float* vv = g_v + (size_t)(b * Ldim) * Edim + h * Ddim + d;
    const float* wp = g_w + bh * Ldim;

    float acc = 0.f;
#pragma unroll 8
    for (int k = kbase + kq; k < kbase + 256; k += 4)
        acc = fmaf(wp[k], vv[(size_t)k * Edim], acc);

    red[kq][d] = acc;
    __syncthreads();
    if (tid < 64) {
        float s = red[0][tid] + red[1][tid] + red[2][tid] + red[3][tid];
        atomicAdd(&g_ho[b * Edim + h * Ddim + tid], s);
    }
}

// ======================================================================
// Final: out[b, e'] = sum_e ho[b, e] * Wo[e', e]   (warp per output)
// ======================================================================
__global__ void __launch_bounds__(256) out_kernel(const float* __restrict__ Wo,
                                                  float* __restrict__ out)
{
    int gw = (blockIdx.x * blockDim.x + threadIdx.x) >> 5;
    int lane = threadIdx.x & 31;
    int b = gw >> 10;
    int ep = gw & 1023;
    const float* ho = &g_ho[(size_t)b * Edim];
    const float* wr = &Wo[(size_t)ep * Edim];
    float s = 0.f;
    for (int e = lane * 4; e < Edim; e += 128) {
        float4 w4 = *(const float4*)&wr[e];
        float4 h4 = *(const float4*)&ho[e];
        s = fmaf(w4.x, h4.x, s);
        s = fmaf(w4.y, h4.y, s);
        s = fmaf(w4.z, h4.z, s);
        s = fmaf(w4.w, h4.w, s);
    }
#pragma unroll
    for (int off = 16; off; off >>= 1) s += __shfl_xor_sync(0xffffffffu, s, off);
    if (lane == 0) out[(size_t)b * Edim + ep] = s;
}

// ======================================================================
extern "C" void kernel_launch(void* const* d_in, const int* in_sizes, int n_in,
                              void* d_out, int out_size)
{
    const float* Q = (const float*)d_in[0];
    const float* K = (const float*)d_in[1];
    const float* V = (const float*)d_in[2];
    const float* Wq = (const float*)d_in[3];
    const float* Wk = (const float*)d_in[4];
    const float* Wv = (const float*)d_in[5];
    const float* Wo = (const float*)d_in[6];
    float* out = (float*)d_out;

    cudaFuncSetAttribute(proj_mma_kernel, cudaFuncAttributeMaxDynamicSharedMemorySize, PJ_SMEM_BYTES);
    cudaFuncSetAttribute(attn_passA_kernel, cudaFuncAttributeMaxDynamicSharedMemorySize, A_SMEM_BYTES);

    zero_acc_kernel<<<64, 1024>>>();
    proj_mma_kernel<<<dim3(NROWS / 128, Edim / 128, 3), 256, PJ_SMEM_BYTES>>>(Q, K, V, Wq, Wk, Wv);
    attn_passA_kernel<<<dim3(Ldim / 128, NBH), 256, A_SMEM_BYTES>>>();
    attn_passB_kernel<<<dim3(Ldim / 128, NBH, 4), 256>>>();
    gemv_ho_kernel<<<dim3(NBH, Ldim / 256), 256>>>();
    out_kernel<<<256, 256>>>(Wo, out);
}